// round 12
// baseline (speedup 1.0000x reference)
#include <cuda_runtime.h>
#include <cuda_fp16.h>
#include <cuda_pipeline.h>
#include <mma.h>
#include <cstdint>

using namespace nvcuda;

// Problem dims (fixed)
#define Td  4
#define Bd  32
#define Cd  512
#define CVd 2048
#define Nd  256
#define NHd 8
#define DHd 64
#define DVd 256
#define TBd (Td*Bd)      // 128
#define Zd  (TBd*NHd)    // 1024

// ---------------- static scratch ------------------------------------------------
__device__ __align__(256) int8_t g_xs8[(size_t)TBd*Cd *Nd]; // x spikes s8 [z][c][n]
__device__ __align__(256) float  g_qf [(size_t)TBd*Cd *Nd]; // conv outs fp32 [z][m][n]
__device__ __align__(256) float  g_kf [(size_t)TBd*Cd *Nd];
__device__ __align__(256) float  g_vf [(size_t)TBd*CVd*Nd];
__device__ __align__(256) __half g_qh [(size_t)TBd*Cd *Nd]; // spikes fp16 [z][c][n]
__device__ __align__(256) __half g_kh [(size_t)TBd*Cd *Nd];
__device__ __align__(256) __half g_vh [(size_t)TBd*CVd*Nd];
__device__ __align__(256) __half g_kvhi[(size_t)Zd*DHd*DVd];
__device__ __align__(256) __half g_kvlo[(size_t)Zd*DHd*DVd];
__device__ __align__(256) __half g_oh [(size_t)TBd*CVd*Nd]; // attn spikes [z][e][n]
// int8 conv weights (2-term, per-row scale q; w*bnscale ~= (hi*128+lo)*q)
__device__ __align__(256) int8_t g_w8q_h[Cd*Cd];
__device__ __align__(256) int8_t g_w8q_l[Cd*Cd];
__device__ __align__(256) int8_t g_w8k_h[Cd*Cd];
__device__ __align__(256) int8_t g_w8k_l[Cd*Cd];
__device__ __align__(256) int8_t g_w8v_h[CVd*Cd];
__device__ __align__(256) int8_t g_w8v_l[CVd*Cd];
__device__ __align__(256) float  g_qs_q[Cd];
__device__ __align__(256) float  g_qs_k[Cd];
__device__ __align__(256) float  g_qs_v[CVd];
// p conv stays fp16 single-term
__device__ __align__(256) __half g_wp_hi[Cd*CVd];
__device__ __align__(256) __half g_wp_lo[Cd*CVd];
__device__ __align__(256) float  g_b2d_p[Cd*128];

// ---------------- prep: int8 2-term weight decomposition ------------------------
__global__ void prep_w_s8(const float* __restrict__ w, const float* __restrict__ scale,
                          int8_t* __restrict__ hi, int8_t* __restrict__ lo,
                          float* __restrict__ qs, int M, int K)
{
    int m = blockIdx.x * 8 + (threadIdx.x >> 5);
    int lane = threadIdx.x & 31;
    if (m >= M) return;
    const float* wr = w + (size_t)m * K;
    float sc = scale[m];
    float mx = 0.f;
    for (int k = lane; k < K; k += 32) mx = fmaxf(mx, fabsf(wr[k] * sc));
#pragma unroll
    for (int o = 16; o; o >>= 1) mx = fmaxf(mx, __shfl_xor_sync(0xffffffffu, mx, o));
    float q = mx / 16256.0f;
    float invq = (q > 0.f) ? 1.0f / q : 0.f;
    for (int k = lane; k < K; k += 32) {
        float t = wr[k] * sc * invq;                 // |t| <= 16256
        float h = rintf(t * (1.0f / 128.0f));        // |h| <= 127
        float l = rintf(t - h * 128.0f);             // |l| <= 64
        hi[(size_t)m * K + k] = (int8_t)h;
        lo[(size_t)m * K + k] = (int8_t)l;
    }
    if (lane == 0) qs[m] = q * 0.125f;               // fold spike /8
}

// ---------------- prep for p conv (fp16) ----------------------------------------
__global__ void prep_w(const float* __restrict__ w, const float* __restrict__ scale,
                       __half* __restrict__ hi, __half* __restrict__ lo, int M, int K)
{
    int i = blockIdx.x * blockDim.x + threadIdx.x;
    if (i >= M * K) return;
    float v = w[i] * scale[i / K];
    __half h = __float2half_rn(v);
    hi[i] = h;
    lo[i] = __float2half_rn(v - __half2float(h));
}

__global__ void prep_b(const float* __restrict__ bias, float* __restrict__ b2d, int M)
{
    int i = blockIdx.x * blockDim.x + threadIdx.x;
    if (i >= M * 128) return;
    b2d[i] = bias[i >> 7];
}

// ---------------- SFA scan x -> s8 spikes (layout preserved, vectorized x4) -----
__global__ void sfa_s84(const float4* __restrict__ in, uchar4* __restrict__ out, int perT4)
{
    int i = blockIdx.x * blockDim.x + threadIdx.x;
    if (i >= perT4) return;
    float h0 = 0.f, h1 = 0.f, h2 = 0.f, h3 = 0.f;
#pragma unroll
    for (int t = 0; t < Td; ++t) {
        float4 v = in[(size_t)t * perT4 + i];
        float u0 = h0 + v.x, u1 = h1 + v.y, u2 = h2 + v.z, u3 = h3 + v.w;
        float s0 = rintf(fminf(fmaxf(u0, 0.f), 8.f));
        float s1 = rintf(fminf(fmaxf(u1, 0.f), 8.f));
        float s2 = rintf(fminf(fmaxf(u2, 0.f), 8.f));
        float s3 = rintf(fminf(fmaxf(u3, 0.f), 8.f));
        h0 = u0 - s0; h1 = u1 - s1; h2 = u2 - s2; h3 = u3 - s3;
        out[(size_t)t * perT4 + i] =
            make_uchar4((unsigned char)s0, (unsigned char)s1,
                        (unsigned char)s2, (unsigned char)s3);   // 0..8, s8-safe
    }
}

// ---------------- SFA scan, vectorized x4: fp32 -> fp16 spikes (R9, unchanged) --
__global__ void sfa_f2h4(const float4* __restrict__ in, uint2* __restrict__ out, int perT4)
{
    int i = blockIdx.x * blockDim.x + threadIdx.x;
    if (i >= perT4) return;
    float h0 = 0.f, h1 = 0.f, h2 = 0.f, h3 = 0.f;
#pragma unroll
    for (int t = 0; t < Td; ++t) {
        float4 v = in[(size_t)t * perT4 + i];
        float u0 = h0 + v.x, u1 = h1 + v.y, u2 = h2 + v.z, u3 = h3 + v.w;
        float s0 = rintf(fminf(fmaxf(u0, 0.f), 8.f));
        float s1 = rintf(fminf(fmaxf(u1, 0.f), 8.f));
        float s2 = rintf(fminf(fmaxf(u2, 0.f), 8.f));
        float s3 = rintf(fminf(fmaxf(u3, 0.f), 8.f));
        h0 = u0 - s0; h1 = u1 - s1; h2 = u2 - s2; h3 = u3 - s3;
        __half2 lo = __floats2half2_rn(s0 * 0.125f, s1 * 0.125f);
        __half2 hi = __floats2half2_rn(s2 * 0.125f, s3 * 0.125f);
        uint2 o;
        o.x = *(const unsigned*)&lo;
        o.y = *(const unsigned*)&hi;
        out[(size_t)t * perT4 + i] = o;
    }
}

// ---------------- s8 conv GEMM (q/k/v): wmma s8 16x16x16, 2-term weights --------
// Y[m][n] = qs[m]*(acc_hi*128+acc_lo) + bias[m],  acc = sum_k W8[m][k]*s8[k][n]
// Block tile 128m x 128n, BK=64, 8 warps (4x2), warp tile 32m x 64n.
// smem/stage: Ahi 128x80B + Alo 128x80B + B 64x144B = 29696 B; 2 stages.
static constexpr int S8_AL  = 10240;
static constexpr int S8_B   = 20480;
static constexpr int S8_ST  = 29696;
static constexpr int S8_SMEM = 2 * S8_ST;        // 59392 B

__global__ void __launch_bounds__(256)
conv_s8(const int8_t* __restrict__ Whi, const int8_t* __restrict__ Wlo,
        const int8_t* __restrict__ Ball, const float* __restrict__ qs,
        const float* __restrict__ bias, float* __restrict__ Yall, int M, int K)
{
    extern __shared__ __align__(256) unsigned char sm[];
    const int tid = threadIdx.x, warp = tid >> 5, lane = tid & 31;
    const int wy = warp >> 1, wx = warp & 1;
    const int mBase = blockIdx.y * 128, nBase = blockIdx.x * 128;

    const int8_t* B = Ball + (size_t)blockIdx.z * K * Nd;   // [c][n] rows
    float*        Y = Yall + (size_t)blockIdx.z * M * Nd;

    const int ar = tid >> 1, ac = (tid & 1) * 32;   // A: 128 rows x 64 k-bytes
    const int br = tid >> 2, bc = (tid & 3) * 32;   // B: 64 k-rows x 128 n-bytes

    auto load_stage = [&](int s, int kb) {
        unsigned char* st = sm + s * S8_ST;
        const int8_t* gh = Whi + (size_t)(mBase + ar) * K + kb + ac;
        const int8_t* gl = Wlo + (size_t)(mBase + ar) * K + kb + ac;
        __pipeline_memcpy_async(st + ar * 80 + ac,                 gh,      16);
        __pipeline_memcpy_async(st + ar * 80 + ac + 16,            gh + 16, 16);
        __pipeline_memcpy_async(st + S8_AL + ar * 80 + ac,         gl,      16);
        __pipeline_memcpy_async(st + S8_AL + ar * 80 + ac + 16,    gl + 16, 16);
        const int8_t* gb = B + (size_t)(kb + br) * Nd + nBase + bc;
        __pipeline_memcpy_async(st + S8_B + br * 144 + bc,         gb,      16);
        __pipeline_memcpy_async(st + S8_B + br * 144 + bc + 16,    gb + 16, 16);
    };

    wmma::fragment<wmma::accumulator, 16, 16, 16, int> acch[2][4], accl[2][4];
#pragma unroll
    for (int i = 0; i < 2; ++i)
#pragma unroll
        for (int j = 0; j < 4; ++j) {
            wmma::fill_fragment(acch[i][j], 0);
            wmma::fill_fragment(accl[i][j], 0);
        }

    load_stage(0, 0);
    __pipeline_commit();

    int rs = 0;
    for (int kb = 0; kb < K; kb += 64) {
        __pipeline_wait_prior(0);
        __syncthreads();

        if (kb + 64 < K) load_stage(rs ^ 1, kb + 64);
        __pipeline_commit();

        const signed char* ap = (const signed char*)(sm + rs * S8_ST);
        const signed char* lp = (const signed char*)(sm + rs * S8_ST + S8_AL);
        const signed char* bp = (const signed char*)(sm + rs * S8_ST + S8_B);
#pragma unroll
        for (int kk = 0; kk < 64; kk += 16) {
            wmma::fragment<wmma::matrix_a, 16, 16, 16, signed char, wmma::row_major> ah[2], al[2];
#pragma unroll
            for (int i = 0; i < 2; ++i) {
                wmma::load_matrix_sync(ah[i], ap + (wy * 32 + i * 16) * 80 + kk, 80);
                wmma::load_matrix_sync(al[i], lp + (wy * 32 + i * 16) * 80 + kk, 80);
            }
#pragma unroll
            for (int j = 0; j < 4; ++j) {
                wmma::fragment<wmma::matrix_b, 16, 16, 16, signed char, wmma::row_major> bf;
                wmma::load_matrix_sync(bf, bp + kk * 144 + wx * 64 + j * 16, 144);
#pragma unroll
                for (int i = 0; i < 2; ++i) {
                    wmma::mma_sync(acch[i][j], ah[i], bf, acch[i][j]);
                    wmma::mma_sync(accl[i][j], al[i], bf, accl[i][j]);
                }
            }
        }
        rs ^= 1;
    }

    // combine hi/lo inside fragments (identical element mapping): acc = hi*128 + lo
#pragma unroll
    for (int i = 0; i < 2; ++i)
#pragma unroll
        for (int j = 0; j < 4; ++j)
#pragma unroll
            for (int e = 0; e < acch[i][j].num_elements; ++e)
                acch[i][j].x[e] = acch[i][j].x[e] * 128 + accl[i][j].x[e];

    // epilogue: stage 32x32 int tiles (ldm=36, proven), scale + bias, store fp32
    __syncthreads();                               // everyone done reading smem tiles
    int* st = (int*)sm + warp * (32 * 36);
    const int mRow = mBase + wy * 32 + lane;
    const float qv = qs[mRow], bv = bias[mRow];
#pragma unroll
    for (int ch = 0; ch < 2; ++ch) {
#pragma unroll
        for (int i = 0; i < 2; ++i)
#pragma unroll
            for (int jj = 0; jj < 2; ++jj)
                wmma::store_matrix_sync(st + (i * 16) * 36 + jj * 16,
                                        acch[i][ch * 2 + jj], 36, wmma::mem_row_major);
        __syncwarp();
        __align__(16) float tmp[32];
#pragma unroll
        for (int c = 0; c < 32; ++c)
            tmp[c] = (float)st[lane * 36 + c] * qv + bv;
        float* yp = Y + (size_t)mRow * Nd + nBase + wx * 64 + ch * 32;
#pragma unroll
        for (int c = 0; c < 8; ++c) ((float4*)yp)[c] = ((const float4*)tmp)[c];
        __syncwarp();
    }
}

// ---------------- conv GEMM single-term fp16 (p conv): R9, unchanged ------------
static constexpr int P_OFF_B = 18432;                // A: 128x72 halves
static constexpr int P_ST    = 35840;                // + B: 64x136 halves
static constexpr int P_SMEM  = 2 * P_ST;             // 71680 B

__global__ void __launch_bounds__(256)
conv_wmma1(const __half* __restrict__ A, const __half* __restrict__ Ball,
           const float* __restrict__ b2d, float* __restrict__ Yall, int M, int K)
{
    extern __shared__ __align__(256) unsigned char sm[];

    const int tid = threadIdx.x;
    const int warp = tid >> 5;
    const int wy = warp >> 1, wx = warp & 1;
    const int mBase = blockIdx.y * 128, nBase = blockIdx.x * 128;

    const __half* B = Ball + (size_t)blockIdx.z * K * Nd;
    float*        Y = Yall + (size_t)blockIdx.z * M * Nd;

    const int ar = tid >> 1, ac = (tid & 1) * 32;
    const int br = tid >> 2, bc = (tid & 3) * 32;

    auto load_stage = [&](int s, int kb) {
        __half* ah = (__half*)(sm + s * P_ST);
        __half* bb = (__half*)(sm + s * P_ST + P_OFF_B);
        const __half* ga = A + (size_t)(mBase + ar) * K + kb + ac;
#pragma unroll
        for (int q = 0; q < 4; ++q)
            __pipeline_memcpy_async(ah + ar * 72 + ac + q * 8, ga + q * 8, 16);
        const __half* gb = B + (size_t)(kb + br) * Nd + nBase + bc;
#pragma unroll
        for (int q = 0; q < 4; ++q)
            __pipeline_memcpy_async(bb + br * 136 + bc + q * 8, gb + q * 8, 16);
    };

    wmma::fragment<wmma::accumulator, 16, 16, 16, float> acc[2][4];
#pragma unroll
    for (int i = 0; i < 2; ++i)
#pragma unroll
        for (int j = 0; j < 4; ++j)
            wmma::load_matrix_sync(acc[i][j],
                b2d + (size_t)(mBase + wy * 32 + i * 16) * 128 + wx * 64 + j * 16,
                128, wmma::mem_row_major);

    load_stage(0, 0);
    __pipeline_commit();

    int rs = 0;
    for (int kb = 0; kb < K; kb += 64) {
        __pipeline_wait_prior(0);
        __syncthreads();

        int nk = kb + 64;
        if (nk < K) load_stage(rs ^ 1, nk);
        __pipeline_commit();

        const __half* ahp = (const __half*)(sm + rs * P_ST);
        const __half* bbp = (const __half*)(sm + rs * P_ST + P_OFF_B);
#pragma unroll
        for (int kk = 0; kk < 64; kk += 16) {
            wmma::fragment<wmma::matrix_a, 16, 16, 16, half, wmma::row_major> ah[2];
#pragma unroll
            for (int i = 0; i < 2; ++i)
                wmma::load_matrix_sync(ah[i], ahp + (wy * 32 + i * 16) * 72 + kk, 72);
#pragma unroll
            for (int j = 0; j < 4; ++j) {
                wmma::fragment<wmma::matrix_b, 16, 16, 16, half, wmma::row_major> bf;
                wmma::load_matrix_sync(bf, bbp + kk * 136 + wx * 64 + j * 16, 136);
#pragma unroll
                for (int i = 0; i < 2; ++i)
                    wmma::mma_sync(acc[i][j], ah[i], bf, acc[i][j]);
            }
        }

        rs ^= 1;
    }

#pragma unroll
    for (int i = 0; i < 2; ++i)
#pragma unroll
        for (int j = 0; j < 4; ++j)
            wmma::store_matrix_sync(
                Y + (size_t)(mBase + wy * 32 + i * 16) * Nd + nBase + wx * 64 + j * 16,
                acc[i][j], Nd, wmma::mem_row_major);
}

// ---------------- kv = K V^T with fused lossless hi/lo split (R9, unchanged) ----
__global__ void __launch_bounds__(256)
kv_wmma()
{
    __shared__ __align__(16) float stg[8][16 * 68];

    const int tid = threadIdx.x, warp = tid >> 5, lane = tid & 31;
    const int wy = warp >> 1, wx = warp & 1;
    const int z = blockIdx.x;
    const int tb = z >> 3, h = z & 7;

    const __half* Kp = g_kh + ((size_t)tb * Cd  + h * DHd) * Nd;
    const __half* Vp = g_vh + ((size_t)tb * CVd + h * DVd) * Nd;
    __half* KVh = g_kvhi + (size_t)z * DHd * DVd;
    __half* KVl = g_kvlo + (size_t)z * DHd * DVd;

    wmma::fragment<wmma::accumulator, 16, 16, 16, float> acc[8];
#pragma unroll
    for (int j = 0; j < 8; ++j) wmma::fill_fragment(acc[j], 0.f);

    for (int k0 = 0; k0 < Nd; k0 += 16) {
        wmma::fragment<wmma::matrix_a, 16, 16, 16, half, wmma::row_major> a;
        wmma::load_matrix_sync(a, Kp + (size_t)(wy * 16) * Nd + k0, Nd);
#pragma unroll
        for (int j = 0; j < 8; ++j) {
            wmma::fragment<wmma::matrix_b, 16, 16, 16, half, wmma::col_major> b;
            wmma::load_matrix_sync(b, Vp + (size_t)(wx * 128 + j * 16) * Nd + k0, Nd);
            wmma::mma_sync(acc[j], a, b, acc[j]);
        }
    }

    float* st = stg[warp];
#pragma unroll
    for (int ch = 0; ch < 2; ++ch) {
#pragma unroll
        for (int j = 0; j < 4; ++j)
            wmma::store_matrix_sync(st + j * 16, acc[ch * 4 + j], 68, wmma::mem_row_major);
        __syncwarp();
        const int r = lane & 15, cs = (lane >> 4) * 32;
        __align__(16) __half tH[32], tL[32];
#pragma unroll
        for (int c = 0; c < 32; ++c) {
            float v = st[r * 68 + cs + c];
            __half hh = __float2half_rn(v);
            tH[c] = hh;
            tL[c] = __float2half_rn(v - __half2float(hh));
        }
        size_t off = (size_t)(wy * 16 + r) * DVd + wx * 128 + ch * 64 + cs;
#pragma unroll
        for (int c = 0; c < 4; ++c) {
            ((uint4*)(KVh + off))[c] = ((const uint4*)tH)[c];
            ((uint4*)(KVl + off))[c] = ((const uint4*)tL)[c];
        }
        __syncwarp();
    }
}

// ---------------- attention O = 0.25 * kv^T Q, fused SFA -> oh (R9, unchanged) --
__global__ void __launch_bounds__(256)
av_fused()
{
    __shared__ __align__(16) float stg[8][32 * 36];

    const int tid = threadIdx.x, warp = tid >> 5, lane = tid & 31;
    const int wy = warp >> 1, wx = warp & 1;
    const int zp = blockIdx.z;
    const int b = zp >> 3, hd = zp & 7;
    const int eBase = blockIdx.y * 128, nBase = blockIdx.x * 64;

    float* st = stg[warp];
    const int eRow = eBase + wy * 32 + lane;

    float hreg[32];
#pragma unroll
    for (int c = 0; c < 32; ++c) hreg[c] = 0.f;

    for (int t = 0; t < Td; ++t) {
        const int tb = t * Bd + b;
        const size_t zkv = (size_t)(tb * NHd + hd) * DHd * DVd;
        const __half* KVh = g_kvhi + zkv;
        const __half* KVl = g_kvlo + zkv;
        const __half* Qp  = g_qh + ((size_t)tb * Cd + hd * DHd) * Nd;

        wmma::fragment<wmma::accumulator, 16, 16, 16, float> acc[2][2];
#pragma unroll
        for (int i = 0; i < 2; ++i)
#pragma unroll
            for (int j = 0; j < 2; ++j) wmma::fill_fragment(acc[i][j], 0.f);

#pragma unroll
        for (int k0 = 0; k0 < DHd; k0 += 16) {
            wmma::fragment<wmma::matrix_a, 16, 16, 16, half, wmma::col_major> ah[2], al[2];
#pragma unroll
            for (int i = 0; i < 2; ++i) {
                wmma::load_matrix_sync(ah[i], KVh + (size_t)k0 * DVd + eBase + wy * 32 + i * 16, DVd);
                wmma::load_matrix_sync(al[i], KVl + (size_t)k0 * DVd + eBase + wy * 32 + i * 16, DVd);
            }
#pragma unroll
            for (int j = 0; j < 2; ++j) {
                wmma::fragment<wmma::matrix_b, 16, 16, 16, half, wmma::row_major> bf;
                wmma::load_matrix_sync(bf, Qp + (size_t)k0 * Nd + nBase + wx * 32 + j * 16, Nd);
#pragma unroll
                for (int i = 0; i < 2; ++i) {
                    wmma::mma_sync(acc[i][j], ah[i], bf, acc[i][j]);
                    wmma::mma_sync(acc[i][j], al[i], bf, acc[i][j]);
                }
            }
        }

#pragma unroll
        for (int i = 0; i < 2; ++i)
#pragma unroll
            for (int j = 0; j < 2; ++j)
                wmma::store_matrix_sync(st + (i * 16) * 36 + j * 16, acc[i][j], 36,
                                        wmma::mem_row_major);
        __syncwarp();

        __align__(16) __half tmp[32];
#pragma unroll
        for (int c = 0; c < 32; ++c) {
            float u = hreg[c] + st[lane * 36 + c] * 0.25f;
            float s = rintf(fminf(fmaxf(u, 0.f), 8.f));
            hreg[c] = u - s;
            tmp[c] = __float2half_rn(s * 0.125f);
        }
        __half* yp = g_oh + ((size_t)tb * CVd + hd * DVd + eRow) * Nd + nBase + wx * 32;
#pragma unroll
        for (int c = 0; c < 4; ++c) ((uint4*)yp)[c] = ((const uint4*)tmp)[c];
        __syncwarp();
    }
}

// ---------------- launch --------------------------------------------------------
extern "C" void kernel_launch(void* const* d_in, const int* in_sizes, int n_in,
                              void* d_out, int out_size)
{
    (void)in_sizes; (void)n_in; (void)out_size;

    const float* x       = (const float*)d_in[0];
    const float* wq      = (const float*)d_in[1];
    const float* wk      = (const float*)d_in[2];
    const float* wv      = (const float*)d_in[3];
    const float* wp      = (const float*)d_in[4];
    const float* q_scale = (const float*)d_in[5];
    const float* q_bias  = (const float*)d_in[6];
    const float* k_scale = (const float*)d_in[7];
    const float* k_bias  = (const float*)d_in[8];
    const float* v_scale = (const float*)d_in[9];
    const float* v_bias  = (const float*)d_in[10];
    const float* p_scale = (const float*)d_in[11];
    const float* p_bias  = (const float*)d_in[12];
    float* out = (float*)d_out;

    void* p;
    cudaGetSymbolAddress(&p, g_xs8);   int8_t* xs8 = (int8_t*)p;
    cudaGetSymbolAddress(&p, g_qf);    float*  qf  = (float*)p;
    cudaGetSymbolAddress(&p, g_kf);    float*  kf  = (float*)p;
    cudaGetSymbolAddress(&p, g_vf);    float*  vf  = (float*)p;
    cudaGetSymbolAddress(&p, g_qh);    __half* qh  = (__half*)p;
    cudaGetSymbolAddress(&p, g_kh);    __half* kh  = (__half*)p;
    cudaGetSymbolAddress(&p, g_vh);    __half* vh  = (__half*)p;
    cudaGetSymbolAddress(&p, g_oh);    __half* oh  = (__half*)p;
    cudaGetSymbolAddress(&p, g_w8q_h); int8_t* wqh8 = (int8_t*)p;
    cudaGetSymbolAddress(&p, g_w8q_l); int8_t* wql8 = (int8_t*)p;
    cudaGetSymbolAddress(&p, g_w8k_h); int8_t* wkh8 = (int8_t*)p;
    cudaGetSymbolAddress(&p, g_w8k_l); int8_t* wkl8 = (int8_t*)p;
    cudaGetSymbolAddress(&p, g_w8v_h); int8_t* wvh8 = (int8_t*)p;
    cudaGetSymbolAddress(&p, g_w8v_l); int8_t* wvl8 = (int8_t*)p;
    cudaGetSymbolAddress(&p, g_qs_q);  float*  qsq = (float*)p;
    cudaGetSymbolAddress(&p, g_qs_k);  float*  qsk = (float*)p;
    cudaGetSymbolAddress(&p, g_qs_v);  float*  qsv = (float*)p;
    cudaGetSymbolAddress(&p, g_wp_hi); __half* wph = (__half*)p;
    cudaGetSymbolAddress(&p, g_wp_lo); __half* wpl = (__half*)p;
    cudaGetSymbolAddress(&p, g_b2d_p); float*  b2p = (float*)p;

    cudaFuncSetAttribute(conv_s8,    cudaFuncAttributeMaxDynamicSharedMemorySize, S8_SMEM);
    cudaFuncSetAttribute(conv_wmma1, cudaFuncAttributeMaxDynamicSharedMemorySize, P_SMEM);

    const int perT1 = Bd * Cd  * Nd;   //  4,194,304
    const int perTv = Bd * CVd * Nd;   // 16,777,216

    // 0. weight prep: int8 2-term for q/k/v, fp16 single for p
    prep_w_s8<<<Cd  / 8, 256>>>(wq, q_scale, wqh8, wql8, qsq, Cd,  Cd);
    prep_w_s8<<<Cd  / 8, 256>>>(wk, k_scale, wkh8, wkl8, qsk, Cd,  Cd);
    prep_w_s8<<<CVd / 8, 256>>>(wv, v_scale, wvh8, wvl8, qsv, CVd, Cd);
    prep_w<<<(Cd * CVd + 255) / 256, 256>>>(wp, p_scale, wph, wpl, Cd, CVd);
    prep_b<<<(Cd * 128 + 255) / 256, 256>>>(p_bias, b2p, Cd);

    // 1. head spikes as s8, layout [z][c][n] (no transpose needed)
    sfa_s84<<<perT1 / 4 / 256, 256>>>((const float4*)x, (uchar4*)xs8, perT1 / 4);

    // 2. q/k/v conv + BN (s8 wmma, 2-term weights)
    conv_s8<<<dim3(2, Cd  / 128, TBd), 256, S8_SMEM>>>(wqh8, wql8, xs8, qsq, q_bias, qf, Cd,  Cd);
    conv_s8<<<dim3(2, Cd  / 128, TBd), 256, S8_SMEM>>>(wkh8, wkl8, xs8, qsk, k_bias, kf, Cd,  Cd);
    conv_s8<<<dim3(2, CVd / 128, TBd), 256, S8_SMEM>>>(wvh8, wvl8, xs8, qsv, v_bias, vf, CVd, Cd);

    // 3. spike q/k/v (fp16)
    sfa_f2h4<<<perT1 / 4 / 256, 256>>>((const float4*)qf, (uint2*)qh, perT1 / 4);
    sfa_f2h4<<<perT1 / 4 / 256, 256>>>((const float4*)kf, (uint2*)kh, perT1 / 4);
    sfa_f2h4<<<perTv / 4 / 256, 256>>>((const float4*)vf, (uint2*)vh, perTv / 4);

    // 4. linear attention: kv = K V^T (fused hi/lo split), O = 0.25 kv^T Q (fused SFA)
    kv_wmma<<<Zd, 256>>>();
    av_fused<<<dim3(4, 2, Bd * NHd), 256>>>();

    // 5. projection conv + BN -> fp32 output (single fp16 term)
    conv_wmma1<<<dim3(2, 4, TBd), 256, P_SMEM>>>(wph, oh, b2p, out, Cd, CVd);
}

// round 13
// speedup vs baseline: 2.8449x; 2.8449x over previous
#include <cuda_runtime.h>
#include <cuda_fp16.h>
#include <cuda_pipeline.h>
#include <mma.h>
#include <cstdint>

using namespace nvcuda;

// Problem dims (fixed)
#define Td  4
#define Bd  32
#define Cd  512
#define CVd 2048
#define Nd  256
#define NHd 8
#define DHd 64
#define DVd 256
#define TBd (Td*Bd)      // 128
#define Zd  (TBd*NHd)    // 1024

// ---------------- static scratch ------------------------------------------------
__device__ __align__(256) __half g_xs [(size_t)TBd*Cd *Nd];
__device__ __align__(256) float  g_qf [(size_t)TBd*Cd *Nd];
__device__ __align__(256) float  g_kf [(size_t)TBd*Cd *Nd];
__device__ __align__(256) float  g_vf [(size_t)TBd*CVd*Nd];
__device__ __align__(256) __half g_qh [(size_t)TBd*Cd *Nd];
__device__ __align__(256) __half g_kh [(size_t)TBd*Cd *Nd];
__device__ __align__(256) __half g_vh [(size_t)TBd*CVd*Nd];
__device__ __align__(256) __half g_kvhi[(size_t)Zd*DHd*DVd];
__device__ __align__(256) __half g_kvlo[(size_t)Zd*DHd*DVd];
__device__ __align__(256) __half g_oh [(size_t)TBd*CVd*Nd];   // attn spikes [z][e][n]
// folded single-term fp16 weights (scale folded in)
__device__ __align__(256) __half g_wq[Cd*Cd];
__device__ __align__(256) __half g_wk[Cd*Cd];
__device__ __align__(256) __half g_wv[CVd*Cd];
__device__ __align__(256) __half g_wp[Cd*CVd];
// bias broadcast tables [M][128] for accumulator init
__device__ __align__(256) float g_b2d_q[Cd*128], g_b2d_k[Cd*128];
__device__ __align__(256) float g_b2d_v[CVd*128], g_b2d_p[Cd*128];

// ---------------- prep: fold BN scale into weights (single fp16 term) -----------
__global__ void prep_w1(const float* __restrict__ w, const float* __restrict__ scale,
                        __half* __restrict__ dst, int M, int K)
{
    int i = blockIdx.x * blockDim.x + threadIdx.x;
    if (i >= M * K) return;
    dst[i] = __float2half_rn(w[i] * scale[i / K]);
}

__global__ void prep_b(const float* __restrict__ bias, float* __restrict__ b2d, int M)
{
    int i = blockIdx.x * blockDim.x + threadIdx.x;
    if (i >= M * 128) return;
    b2d[i] = bias[i >> 7];
}

// ---------------- SFA scan, vectorized x4: fp32 -> fp16 spikes ------------------
__global__ void sfa_f2h4(const float4* __restrict__ in, uint2* __restrict__ out, int perT4)
{
    int i = blockIdx.x * blockDim.x + threadIdx.x;
    if (i >= perT4) return;
    float h0 = 0.f, h1 = 0.f, h2 = 0.f, h3 = 0.f;
#pragma unroll
    for (int t = 0; t < Td; ++t) {
        float4 v = in[(size_t)t * perT4 + i];
        float u0 = h0 + v.x, u1 = h1 + v.y, u2 = h2 + v.z, u3 = h3 + v.w;
        float s0 = rintf(fminf(fmaxf(u0, 0.f), 8.f));
        float s1 = rintf(fminf(fmaxf(u1, 0.f), 8.f));
        float s2 = rintf(fminf(fmaxf(u2, 0.f), 8.f));
        float s3 = rintf(fminf(fmaxf(u3, 0.f), 8.f));
        h0 = u0 - s0; h1 = u1 - s1; h2 = u2 - s2; h3 = u3 - s3;
        __half2 lo = __floats2half2_rn(s0 * 0.125f, s1 * 0.125f);
        __half2 hi = __floats2half2_rn(s2 * 0.125f, s3 * 0.125f);
        uint2 o;
        o.x = *(const unsigned*)&lo;
        o.y = *(const unsigned*)&hi;
        out[(size_t)t * perT4 + i] = o;
    }
}

// ---------------- conv GEMM single-term fp16: BK=64, 2-stage cp.async -----------
// Y[z][m][n] = W[m][k] * B[z][k][n] + bias[m]
// Block tile 128x128, 8 warps (4x2), warp tile 32x64.
static constexpr int P_OFF_B = 18432;                // A: 128x72 halves
static constexpr int P_ST    = 35840;                // + B: 64x136 halves
static constexpr int P_SMEM  = 2 * P_ST;             // 71680 B -> 2 CTAs/SM

__global__ void __launch_bounds__(256)
conv_wmma1(const __half* __restrict__ A, const __half* __restrict__ Ball,
           const float* __restrict__ b2d, float* __restrict__ Yall, int M, int K)
{
    extern __shared__ __align__(256) unsigned char sm[];

    const int tid = threadIdx.x;
    const int warp = tid >> 5;
    const int wy = warp >> 1, wx = warp & 1;
    const int mBase = blockIdx.y * 128, nBase = blockIdx.x * 128;

    const __half* B = Ball + (size_t)blockIdx.z * K * Nd;
    float*        Y = Yall + (size_t)blockIdx.z * M * Nd;

    const int ar = tid >> 1, ac = (tid & 1) * 32;    // A: 128 rows x 64 k
    const int br = tid >> 2, bc = (tid & 3) * 32;    // B: 64 k x 128 n

    auto load_stage = [&](int s, int kb) {
        __half* ah = (__half*)(sm + s * P_ST);
        __half* bb = (__half*)(sm + s * P_ST + P_OFF_B);
        const __half* ga = A + (size_t)(mBase + ar) * K + kb + ac;
#pragma unroll
        for (int q = 0; q < 4; ++q)
            __pipeline_memcpy_async(ah + ar * 72 + ac + q * 8, ga + q * 8, 16);
        const __half* gb = B + (size_t)(kb + br) * Nd + nBase + bc;
#pragma unroll
        for (int q = 0; q < 4; ++q)
            __pipeline_memcpy_async(bb + br * 136 + bc + q * 8, gb + q * 8, 16);
    };

    wmma::fragment<wmma::accumulator, 16, 16, 16, float> acc[2][4];
#pragma unroll
    for (int i = 0; i < 2; ++i)
#pragma unroll
        for (int j = 0; j < 4; ++j)
            wmma::load_matrix_sync(acc[i][j],
                b2d + (size_t)(mBase + wy * 32 + i * 16) * 128 + wx * 64 + j * 16,
                128, wmma::mem_row_major);

    load_stage(0, 0);
    __pipeline_commit();

    int rs = 0;
    for (int kb = 0; kb < K; kb += 64) {
        __pipeline_wait_prior(0);    // chunk kb landed
        __syncthreads();             // all warps done with the other stage

        int nk = kb + 64;
        if (nk < K) load_stage(rs ^ 1, nk);
        __pipeline_commit();

        const __half* ahp = (const __half*)(sm + rs * P_ST);
        const __half* bbp = (const __half*)(sm + rs * P_ST + P_OFF_B);
#pragma unroll
        for (int kk = 0; kk < 64; kk += 16) {
            wmma::fragment<wmma::matrix_a, 16, 16, 16, half, wmma::row_major> ah[2];
#pragma unroll
            for (int i = 0; i < 2; ++i)
                wmma::load_matrix_sync(ah[i], ahp + (wy * 32 + i * 16) * 72 + kk, 72);
#pragma unroll
            for (int j = 0; j < 4; ++j) {
                wmma::fragment<wmma::matrix_b, 16, 16, 16, half, wmma::row_major> bf;
                wmma::load_matrix_sync(bf, bbp + kk * 136 + wx * 64 + j * 16, 136);
#pragma unroll
                for (int i = 0; i < 2; ++i)
                    wmma::mma_sync(acc[i][j], ah[i], bf, acc[i][j]);
            }
        }

        rs ^= 1;
    }

#pragma unroll
    for (int i = 0; i < 2; ++i)
#pragma unroll
        for (int j = 0; j < 4; ++j)
            wmma::store_matrix_sync(
                Y + (size_t)(mBase + wy * 32 + i * 16) * Nd + nBase + wx * 64 + j * 16,
                acc[i][j], Nd, wmma::mem_row_major);
}

// ---------------- kv = K V^T with fused lossless hi/lo split --------------------
__global__ void __launch_bounds__(256)
kv_wmma()
{
    __shared__ __align__(16) float stg[8][16 * 68];

    const int tid = threadIdx.x, warp = tid >> 5, lane = tid & 31;
    const int wy = warp >> 1, wx = warp & 1;
    const int z = blockIdx.x;
    const int tb = z >> 3, h = z & 7;

    const __half* Kp = g_kh + ((size_t)tb * Cd  + h * DHd) * Nd;
    const __half* Vp = g_vh + ((size_t)tb * CVd + h * DVd) * Nd;
    __half* KVh = g_kvhi + (size_t)z * DHd * DVd;
    __half* KVl = g_kvlo + (size_t)z * DHd * DVd;

    wmma::fragment<wmma::accumulator, 16, 16, 16, float> acc[8];
#pragma unroll
    for (int j = 0; j < 8; ++j) wmma::fill_fragment(acc[j], 0.f);

    for (int k0 = 0; k0 < Nd; k0 += 16) {
        wmma::fragment<wmma::matrix_a, 16, 16, 16, half, wmma::row_major> a;
        wmma::load_matrix_sync(a, Kp + (size_t)(wy * 16) * Nd + k0, Nd);
#pragma unroll
        for (int j = 0; j < 8; ++j) {
            wmma::fragment<wmma::matrix_b, 16, 16, 16, half, wmma::col_major> b;
            wmma::load_matrix_sync(b, Vp + (size_t)(wx * 128 + j * 16) * Nd + k0, Nd);
            wmma::mma_sync(acc[j], a, b, acc[j]);
        }
    }

    float* st = stg[warp];
#pragma unroll
    for (int ch = 0; ch < 2; ++ch) {
#pragma unroll
        for (int j = 0; j < 4; ++j)
            wmma::store_matrix_sync(st + j * 16, acc[ch * 4 + j], 68, wmma::mem_row_major);
        __syncwarp();
        const int r = lane & 15, cs = (lane >> 4) * 32;
        __align__(16) __half tH[32], tL[32];
#pragma unroll
        for (int c = 0; c < 32; ++c) {
            float v = st[r * 68 + cs + c];
            __half hh = __float2half_rn(v);
            tH[c] = hh;
            tL[c] = __float2half_rn(v - __half2float(hh));   // lossless
        }
        size_t off = (size_t)(wy * 16 + r) * DVd + wx * 128 + ch * 64 + cs;
#pragma unroll
        for (int c = 0; c < 4; ++c) {
            ((uint4*)(KVh + off))[c] = ((const uint4*)tH)[c];
            ((uint4*)(KVl + off))[c] = ((const uint4*)tL)[c];
        }
        __syncwarp();
    }
}

// ---------------- attention O = 0.25 * kv^T Q, fused SFA -> oh ------------------
__global__ void __launch_bounds__(256)
av_fused()
{
    __shared__ __align__(16) float stg[8][32 * 36];

    const int tid = threadIdx.x, warp = tid >> 5, lane = tid & 31;
    const int wy = warp >> 1, wx = warp & 1;
    const int zp = blockIdx.z;
    const int b = zp >> 3, hd = zp & 7;
    const int eBase = blockIdx.y * 128, nBase = blockIdx.x * 64;

    float* st = stg[warp];
    const int eRow = eBase + wy * 32 + lane;

    float hreg[32];
#pragma unroll
    for (int c = 0; c < 32; ++c) hreg[c] = 0.f;

    for (int t = 0; t < Td; ++t) {
        const int tb = t * Bd + b;
        const size_t zkv = (size_t)(tb * NHd + hd) * DHd * DVd;
        const __half* KVh = g_kvhi + zkv;
        const __half* KVl = g_kvlo + zkv;
        const __half* Qp  = g_qh + ((size_t)tb * Cd + hd * DHd) * Nd;

        wmma::fragment<wmma::accumulator, 16, 16, 16, float> acc[2][2];
#pragma unroll
        for (int i = 0; i < 2; ++i)
#pragma unroll
            for (int j = 0; j < 2; ++j) wmma::fill_fragment(acc[i][j], 0.f);

#pragma unroll
        for (int k0 = 0; k0 < DHd; k0 += 16) {
            wmma::fragment<wmma::matrix_a, 16, 16, 16, half, wmma::col_major> ah[2], al[2];
#pragma unroll
            for (int i = 0; i < 2; ++i) {
                wmma::load_matrix_sync(ah[i], KVh + (size_t)k0 * DVd + eBase + wy * 32 + i * 16, DVd);
                wmma::load_matrix_sync(al[i], KVl + (size_t)k0 * DVd + eBase + wy * 32 + i * 16, DVd);
            }
#pragma unroll
            for (int j = 0; j < 2; ++j) {
                wmma::fragment<wmma::matrix_b, 16, 16, 16, half, wmma::row_major> bf;
                wmma::load_matrix_sync(bf, Qp + (size_t)k0 * Nd + nBase + wx * 32 + j * 16, Nd);
#pragma unroll
                for (int i = 0; i < 2; ++i) {
                    wmma::mma_sync(acc[i][j], ah[i], bf, acc[i][j]);
                    wmma::mma_sync(acc[i][j], al[i], bf, acc[i][j]);
                }
            }
        }

#pragma unroll
        for (int i = 0; i < 2; ++i)
#pragma unroll
            for (int j = 0; j < 2; ++j)
                wmma::store_matrix_sync(st + (i * 16) * 36 + j * 16, acc[i][j], 36,
                                        wmma::mem_row_major);
        __syncwarp();

        __align__(16) __half tmp[32];
#pragma unroll
        for (int c = 0; c < 32; ++c) {
            float u = hreg[c] + st[lane * 36 + c] * 0.25f;
            float s = rintf(fminf(fmaxf(u, 0.f), 8.f));
            hreg[c] = u - s;
            tmp[c] = __float2half_rn(s * 0.125f);
        }
        __half* yp = g_oh + ((size_t)tb * CVd + hd * DVd + eRow) * Nd + nBase + wx * 32;
#pragma unroll
        for (int c = 0; c < 4; ++c) ((uint4*)yp)[c] = ((const uint4*)tmp)[c];
        __syncwarp();
    }
}

// ---------------- launch --------------------------------------------------------
extern "C" void kernel_launch(void* const* d_in, const int* in_sizes, int n_in,
                              void* d_out, int out_size)
{
    (void)in_sizes; (void)n_in; (void)out_size;

    const float* x       = (const float*)d_in[0];
    const float* wq      = (const float*)d_in[1];
    const float* wk      = (const float*)d_in[2];
    const float* wv      = (const float*)d_in[3];
    const float* wp      = (const float*)d_in[4];
    const float* q_scale = (const float*)d_in[5];
    const float* q_bias  = (const float*)d_in[6];
    const float* k_scale = (const float*)d_in[7];
    const float* k_bias  = (const float*)d_in[8];
    const float* v_scale = (const float*)d_in[9];
    const float* v_bias  = (const float*)d_in[10];
    const float* p_scale = (const float*)d_in[11];
    const float* p_bias  = (const float*)d_in[12];
    float* out = (float*)d_out;

    void* p;
    cudaGetSymbolAddress(&p, g_xs);    __half* xs  = (__half*)p;
    cudaGetSymbolAddress(&p, g_qf);    float*  qf  = (float*)p;
    cudaGetSymbolAddress(&p, g_kf);    float*  kf  = (float*)p;
    cudaGetSymbolAddress(&p, g_vf);    float*  vf  = (float*)p;
    cudaGetSymbolAddress(&p, g_qh);    __half* qh  = (__half*)p;
    cudaGetSymbolAddress(&p, g_kh);    __half* kh  = (__half*)p;
    cudaGetSymbolAddress(&p, g_vh);    __half* vh  = (__half*)p;
    cudaGetSymbolAddress(&p, g_oh);    __half* oh  = (__half*)p;
    cudaGetSymbolAddress(&p, g_wq);    __half* wqp = (__half*)p;
    cudaGetSymbolAddress(&p, g_wk);    __half* wkp = (__half*)p;
    cudaGetSymbolAddress(&p, g_wv);    __half* wvp = (__half*)p;
    cudaGetSymbolAddress(&p, g_wp);    __half* wpp = (__half*)p;
    cudaGetSymbolAddress(&p, g_b2d_q); float*  b2q = (float*)p;
    cudaGetSymbolAddress(&p, g_b2d_k); float*  b2k = (float*)p;
    cudaGetSymbolAddress(&p, g_b2d_v); float*  b2v = (float*)p;
    cudaGetSymbolAddress(&p, g_b2d_p); float*  b2p = (float*)p;

    cudaFuncSetAttribute(conv_wmma1, cudaFuncAttributeMaxDynamicSharedMemorySize, P_SMEM);

    const int perT1 = Bd * Cd  * Nd;   //  4,194,304
    const int perTv = Bd * CVd * Nd;   // 16,777,216

    // 0. weight folding (single fp16 term) + bias broadcast tables
    prep_w1<<<(Cd  * Cd  + 255) / 256, 256>>>(wq, q_scale, wqp, Cd,  Cd);
    prep_w1<<<(Cd  * Cd  + 255) / 256, 256>>>(wk, k_scale, wkp, Cd,  Cd);
    prep_w1<<<(CVd * Cd  + 255) / 256, 256>>>(wv, v_scale, wvp, CVd, Cd);
    prep_w1<<<(Cd  * CVd + 255) / 256, 256>>>(wp, p_scale, wpp, Cd,  CVd);
    prep_b<<<(Cd  * 128 + 255) / 256, 256>>>(q_bias, b2q, Cd);
    prep_b<<<(Cd  * 128 + 255) / 256, 256>>>(k_bias, b2k, Cd);
    prep_b<<<(CVd * 128 + 255) / 256, 256>>>(v_bias, b2v, CVd);
    prep_b<<<(Cd  * 128 + 255) / 256, 256>>>(p_bias, b2p, Cd);

    // 1. head spikes (fp16), vectorized
    sfa_f2h4<<<perT1 / 4 / 256, 256>>>((const float4*)x, (uint2*)xs, perT1 / 4);

    // 2. q/k/v conv + BN (single-term fp16 wmma, BK=64)
    conv_wmma1<<<dim3(2,  4, TBd), 256, P_SMEM>>>(wqp, xs, b2q, qf, Cd,  Cd);
    conv_wmma1<<<dim3(2,  4, TBd), 256, P_SMEM>>>(wkp, xs, b2k, kf, Cd,  Cd);
    conv_wmma1<<<dim3(2, 16, TBd), 256, P_SMEM>>>(wvp, xs, b2v, vf, CVd, Cd);

    // 3. spike q/k/v (fp16), vectorized
    sfa_f2h4<<<perT1 / 4 / 256, 256>>>((const float4*)qf, (uint2*)qh, perT1 / 4);
    sfa_f2h4<<<perT1 / 4 / 256, 256>>>((const float4*)kf, (uint2*)kh, perT1 / 4);
    sfa_f2h4<<<perTv / 4 / 256, 256>>>((const float4*)vf, (uint2*)vh, perTv / 4);

    // 4. linear attention: kv = K V^T (fused hi/lo split), O = 0.25 kv^T Q (fused SFA)
    kv_wmma<<<Zd, 256>>>();
    av_fused<<<dim3(4, 2, Bd * NHd), 256>>>();

    // 5. projection conv + BN -> fp32 output (single fp16 term)
    conv_wmma1<<<dim3(2, 4, TBd), 256, P_SMEM>>>(wpp, oh, b2p, out, Cd, CVd);
}

// round 14
// speedup vs baseline: 3.0683x; 1.0785x over previous
#include <cuda_runtime.h>
#include <cuda_fp16.h>
#include <cuda_pipeline.h>
#include <mma.h>
#include <cstdint>

using namespace nvcuda;

// Problem dims (fixed)
#define Td  4
#define Bd  32
#define Cd  512
#define CVd 2048
#define Nd  256
#define NHd 8
#define DHd 64
#define DVd 256
#define TBd (Td*Bd)      // 128
#define Zd  (TBd*NHd)    // 1024

// ---------------- static scratch ------------------------------------------------
__device__ __align__(256) __half g_xs [(size_t)TBd*Cd *Nd];   // x spikes
__device__ __align__(256) __half g_qp [(size_t)TBd*Cd *Nd];   // pre-act fp16
__device__ __align__(256) __half g_kp [(size_t)TBd*Cd *Nd];
__device__ __align__(256) __half g_vp [(size_t)TBd*CVd*Nd];
__device__ __align__(256) __half g_qh [(size_t)TBd*Cd *Nd];   // spikes
__device__ __align__(256) __half g_kh [(size_t)TBd*Cd *Nd];
__device__ __align__(256) __half g_vh [(size_t)TBd*CVd*Nd];
__device__ __align__(256) __half g_kv [(size_t)Zd*DHd*DVd];   // kv single fp16
__device__ __align__(256) __half g_oh [(size_t)TBd*CVd*Nd];   // attn spikes [z][e][n]
// folded single-term fp16 weights (scale folded in)
__device__ __align__(256) __half g_wq[Cd*Cd];
__device__ __align__(256) __half g_wk[Cd*Cd];
__device__ __align__(256) __half g_wv[CVd*Cd];
__device__ __align__(256) __half g_wp[Cd*CVd];
// bias broadcast tables [M][128] for accumulator init
__device__ __align__(256) float g_b2d_q[Cd*128], g_b2d_k[Cd*128];
__device__ __align__(256) float g_b2d_v[CVd*128], g_b2d_p[Cd*128];

// ---------------- prep ----------------------------------------------------------
__global__ void prep_w1(const float* __restrict__ w, const float* __restrict__ scale,
                        __half* __restrict__ dst, int M, int K)
{
    int i = blockIdx.x * blockDim.x + threadIdx.x;
    if (i >= M * K) return;
    dst[i] = __float2half_rn(w[i] * scale[i / K]);
}

__global__ void prep_b(const float* __restrict__ bias, float* __restrict__ b2d, int M)
{
    int i = blockIdx.x * blockDim.x + threadIdx.x;
    if (i >= M * 128) return;
    b2d[i] = bias[i >> 7];
}

// ---------------- SFA scan, fp32 in -> fp16 spikes (x pass) ---------------------
__global__ void sfa_f2h4(const float4* __restrict__ in, uint2* __restrict__ out, int perT4)
{
    int i = blockIdx.x * blockDim.x + threadIdx.x;
    if (i >= perT4) return;
    float h0 = 0.f, h1 = 0.f, h2 = 0.f, h3 = 0.f;
#pragma unroll
    for (int t = 0; t < Td; ++t) {
        float4 v = in[(size_t)t * perT4 + i];
        float u0 = h0 + v.x, u1 = h1 + v.y, u2 = h2 + v.z, u3 = h3 + v.w;
        float s0 = rintf(fminf(fmaxf(u0, 0.f), 8.f));
        float s1 = rintf(fminf(fmaxf(u1, 0.f), 8.f));
        float s2 = rintf(fminf(fmaxf(u2, 0.f), 8.f));
        float s3 = rintf(fminf(fmaxf(u3, 0.f), 8.f));
        h0 = u0 - s0; h1 = u1 - s1; h2 = u2 - s2; h3 = u3 - s3;
        __half2 lo = __floats2half2_rn(s0 * 0.125f, s1 * 0.125f);
        __half2 hi = __floats2half2_rn(s2 * 0.125f, s3 * 0.125f);
        uint2 o;
        o.x = *(const unsigned*)&lo;
        o.y = *(const unsigned*)&hi;
        out[(size_t)t * perT4 + i] = o;
    }
}

// ---------------- SFA scan, fp16 pre-act in -> fp16 spikes out ------------------
__global__ void sfa_h2h4(const uint2* __restrict__ in, uint2* __restrict__ out, int perT4)
{
    int i = blockIdx.x * blockDim.x + threadIdx.x;
    if (i >= perT4) return;
    float h0 = 0.f, h1 = 0.f, h2 = 0.f, h3 = 0.f;
#pragma unroll
    for (int t = 0; t < Td; ++t) {
        uint2 v = in[(size_t)t * perT4 + i];
        float2 a = __half22float2(*(const __half2*)&v.x);
        float2 b = __half22float2(*(const __half2*)&v.y);
        float u0 = h0 + a.x, u1 = h1 + a.y, u2 = h2 + b.x, u3 = h3 + b.y;
        float s0 = rintf(fminf(fmaxf(u0, 0.f), 8.f));
        float s1 = rintf(fminf(fmaxf(u1, 0.f), 8.f));
        float s2 = rintf(fminf(fmaxf(u2, 0.f), 8.f));
        float s3 = rintf(fminf(fmaxf(u3, 0.f), 8.f));
        h0 = u0 - s0; h1 = u1 - s1; h2 = u2 - s2; h3 = u3 - s3;
        __half2 lo = __floats2half2_rn(s0 * 0.125f, s1 * 0.125f);
        __half2 hi = __floats2half2_rn(s2 * 0.125f, s3 * 0.125f);
        uint2 o;
        o.x = *(const unsigned*)&lo;
        o.y = *(const unsigned*)&hi;
        out[(size_t)t * perT4 + i] = o;
    }
}

// ---------------- conv GEMM single-term fp16: BK=64, 2-stage cp.async -----------
// Y[z][m][n] = W[m][k] * B[z][k][n] + bias[m];  HOUT: store fp16, else fp32.
static constexpr int P_OFF_B = 18432;                // A: 128x72 halves
static constexpr int P_ST    = 35840;                // + B: 64x136 halves
static constexpr int P_SMEM  = 2 * P_ST;             // 71680 B -> 2 CTAs/SM

template<bool HOUT>
__global__ void __launch_bounds__(256)
conv_wmma1(const __half* __restrict__ A, const __half* __restrict__ Ball,
           const float* __restrict__ b2d, void* __restrict__ Yall, int M, int K)
{
    extern __shared__ __align__(256) unsigned char sm[];

    const int tid = threadIdx.x;
    const int warp = tid >> 5, lane = tid & 31;
    const int wy = warp >> 1, wx = warp & 1;
    const int mBase = blockIdx.y * 128, nBase = blockIdx.x * 128;

    const __half* B = Ball + (size_t)blockIdx.z * K * Nd;

    const int ar = tid >> 1, ac = (tid & 1) * 32;    // A: 128 rows x 64 k
    const int br = tid >> 2, bc = (tid & 3) * 32;    // B: 64 k x 128 n

    auto load_stage = [&](int s, int kb) {
        __half* ah = (__half*)(sm + s * P_ST);
        __half* bb = (__half*)(sm + s * P_ST + P_OFF_B);
        const __half* ga = A + (size_t)(mBase + ar) * K + kb + ac;
#pragma unroll
        for (int q = 0; q < 4; ++q)
            __pipeline_memcpy_async(ah + ar * 72 + ac + q * 8, ga + q * 8, 16);
        const __half* gb = B + (size_t)(kb + br) * Nd + nBase + bc;
#pragma unroll
        for (int q = 0; q < 4; ++q)
            __pipeline_memcpy_async(bb + br * 136 + bc + q * 8, gb + q * 8, 16);
    };

    wmma::fragment<wmma::accumulator, 16, 16, 16, float> acc[2][4];
#pragma unroll
    for (int i = 0; i < 2; ++i)
#pragma unroll
        for (int j = 0; j < 4; ++j)
            wmma::load_matrix_sync(acc[i][j],
                b2d + (size_t)(mBase + wy * 32 + i * 16) * 128 + wx * 64 + j * 16,
                128, wmma::mem_row_major);

    load_stage(0, 0);
    __pipeline_commit();

    int rs = 0;
    for (int kb = 0; kb < K; kb += 64) {
        __pipeline_wait_prior(0);
        __syncthreads();

        int nk = kb + 64;
        if (nk < K) load_stage(rs ^ 1, nk);
        __pipeline_commit();

        const __half* ahp = (const __half*)(sm + rs * P_ST);
        const __half* bbp = (const __half*)(sm + rs * P_ST + P_OFF_B);
#pragma unroll
        for (int kk = 0; kk < 64; kk += 16) {
            wmma::fragment<wmma::matrix_a, 16, 16, 16, half, wmma::row_major> ah[2];
#pragma unroll
            for (int i = 0; i < 2; ++i)
                wmma::load_matrix_sync(ah[i], ahp + (wy * 32 + i * 16) * 72 + kk, 72);
#pragma unroll
            for (int j = 0; j < 4; ++j) {
                wmma::fragment<wmma::matrix_b, 16, 16, 16, half, wmma::row_major> bf;
                wmma::load_matrix_sync(bf, bbp + kk * 136 + wx * 64 + j * 16, 136);
#pragma unroll
                for (int i = 0; i < 2; ++i)
                    wmma::mma_sync(acc[i][j], ah[i], bf, acc[i][j]);
            }
        }

        rs ^= 1;
    }

    if (HOUT) {
        // stage 32x32 chunks (ldm=36, proven) -> fp16 vector stores
        __syncthreads();                 // all warps done reading smem tiles
        float* st = (float*)sm + warp * (32 * 36);
        __half* Y = (__half*)Yall + (size_t)blockIdx.z * M * Nd;
        const int mRow = mBase + wy * 32 + lane;
#pragma unroll
        for (int ch = 0; ch < 2; ++ch) {
#pragma unroll
            for (int i = 0; i < 2; ++i)
#pragma unroll
                for (int jj = 0; jj < 2; ++jj)
                    wmma::store_matrix_sync(st + (i * 16) * 36 + jj * 16,
                                            acc[i][ch * 2 + jj], 36, wmma::mem_row_major);
            __syncwarp();
            __align__(16) __half tmp[32];
#pragma unroll
            for (int c = 0; c < 32; ++c) tmp[c] = __float2half_rn(st[lane * 36 + c]);
            __half* yp = Y + (size_t)mRow * Nd + nBase + wx * 64 + ch * 32;
#pragma unroll
            for (int c = 0; c < 4; ++c) ((uint4*)yp)[c] = ((const uint4*)tmp)[c];
            __syncwarp();
        }
    } else {
        float* Y = (float*)Yall + (size_t)blockIdx.z * M * Nd;
#pragma unroll
        for (int i = 0; i < 2; ++i)
#pragma unroll
            for (int j = 0; j < 4; ++j)
                wmma::store_matrix_sync(
                    Y + (size_t)(mBase + wy * 32 + i * 16) * Nd + nBase + wx * 64 + j * 16,
                    acc[i][j], Nd, wmma::mem_row_major);
    }
}

// ---------------- kv = K V^T -> single fp16 (rn) --------------------------------
__global__ void __launch_bounds__(256)
kv_wmma()
{
    __shared__ __align__(16) float stg[8][16 * 68];

    const int tid = threadIdx.x, warp = tid >> 5, lane = tid & 31;
    const int wy = warp >> 1, wx = warp & 1;
    const int z = blockIdx.x;
    const int tb = z >> 3, h = z & 7;

    const __half* Kp = g_kh + ((size_t)tb * Cd  + h * DHd) * Nd;
    const __half* Vp = g_vh + ((size_t)tb * CVd + h * DVd) * Nd;
    __half* KV = g_kv + (size_t)z * DHd * DVd;

    wmma::fragment<wmma::accumulator, 16, 16, 16, float> acc[8];
#pragma unroll
    for (int j = 0; j < 8; ++j) wmma::fill_fragment(acc[j], 0.f);

    for (int k0 = 0; k0 < Nd; k0 += 16) {
        wmma::fragment<wmma::matrix_a, 16, 16, 16, half, wmma::row_major> a;
        wmma::load_matrix_sync(a, Kp + (size_t)(wy * 16) * Nd + k0, Nd);
#pragma unroll
        for (int j = 0; j < 8; ++j) {
            wmma::fragment<wmma::matrix_b, 16, 16, 16, half, wmma::col_major> b;
            wmma::load_matrix_sync(b, Vp + (size_t)(wx * 128 + j * 16) * Nd + k0, Nd);
            wmma::mma_sync(acc[j], a, b, acc[j]);
        }
    }

    float* st = stg[warp];
#pragma unroll
    for (int ch = 0; ch < 2; ++ch) {
#pragma unroll
        for (int j = 0; j < 4; ++j)
            wmma::store_matrix_sync(st + j * 16, acc[ch * 4 + j], 68, wmma::mem_row_major);
        __syncwarp();
        const int r = lane & 15, cs = (lane >> 4) * 32;
        __align__(16) __half tH[32];
#pragma unroll
        for (int c = 0; c < 32; ++c) tH[c] = __float2half_rn(st[r * 68 + cs + c]);
        size_t off = (size_t)(wy * 16 + r) * DVd + wx * 128 + ch * 64 + cs;
#pragma unroll
        for (int c = 0; c < 4; ++c) ((uint4*)(KV + off))[c] = ((const uint4*)tH)[c];
        __syncwarp();
    }
}

// ---------------- attention O = 0.25 * kv^T Q, fused SFA -> oh ------------------
__global__ void __launch_bounds__(256)
av_fused()
{
    __shared__ __align__(16) float stg[8][32 * 36];

    const int tid = threadIdx.x, warp = tid >> 5, lane = tid & 31;
    const int wy = warp >> 1, wx = warp & 1;
    const int zp = blockIdx.z;
    const int b = zp >> 3, hd = zp & 7;
    const int eBase = blockIdx.y * 128, nBase = blockIdx.x * 64;

    float* st = stg[warp];
    const int eRow = eBase + wy * 32 + lane;

    float hreg[32];
#pragma unroll
    for (int c = 0; c < 32; ++c) hreg[c] = 0.f;

    for (int t = 0; t < Td; ++t) {
        const int tb = t * Bd + b;
        const __half* KV = g_kv + (size_t)(tb * NHd + hd) * DHd * DVd;
        const __half* Qp = g_qh + ((size_t)tb * Cd + hd * DHd) * Nd;

        wmma::fragment<wmma::accumulator, 16, 16, 16, float> acc[2][2];
#pragma unroll
        for (int i = 0; i < 2; ++i)
#pragma unroll
            for (int j = 0; j < 2; ++j) wmma::fill_fragment(acc[i][j], 0.f);

#pragma unroll
        for (int k0 = 0; k0 < DHd; k0 += 16) {
            wmma::fragment<wmma::matrix_a, 16, 16, 16, half, wmma::col_major> ah[2];
#pragma unroll
            for (int i = 0; i < 2; ++i)
                wmma::load_matrix_sync(ah[i], KV + (size_t)k0 * DVd + eBase + wy * 32 + i * 16, DVd);
#pragma unroll
            for (int j = 0; j < 2; ++j) {
                wmma::fragment<wmma::matrix_b, 16, 16, 16, half, wmma::row_major> bf;
                wmma::load_matrix_sync(bf, Qp + (size_t)k0 * Nd + nBase + wx * 32 + j * 16, Nd);
#pragma unroll
                for (int i = 0; i < 2; ++i)
                    wmma::mma_sync(acc[i][j], ah[i], bf, acc[i][j]);
            }
        }

#pragma unroll
        for (int i = 0; i < 2; ++i)
#pragma unroll
            for (int j = 0; j < 2; ++j)
                wmma::store_matrix_sync(st + (i * 16) * 36 + j * 16, acc[i][j], 36,
                                        wmma::mem_row_major);
        __syncwarp();

        __align__(16) __half tmp[32];
#pragma unroll
        for (int c = 0; c < 32; ++c) {
            float u = hreg[c] + st[lane * 36 + c] * 0.25f;
            float s = rintf(fminf(fmaxf(u, 0.f), 8.f));
            hreg[c] = u - s;
            tmp[c] = __float2half_rn(s * 0.125f);
        }
        __half* yp = g_oh + ((size_t)tb * CVd + hd * DVd + eRow) * Nd + nBase + wx * 32;
#pragma unroll
        for (int c = 0; c < 4; ++c) ((uint4*)yp)[c] = ((const uint4*)tmp)[c];
        __syncwarp();
    }
}

// ---------------- launch --------------------------------------------------------
extern "C" void kernel_launch(void* const* d_in, const int* in_sizes, int n_in,
                              void* d_out, int out_size)
{
    (void)in_sizes; (void)n_in; (void)out_size;

    const float* x       = (const float*)d_in[0];
    const float* wq      = (const float*)d_in[1];
    const float* wk      = (const float*)d_in[2];
    const float* wv      = (const float*)d_in[3];
    const float* wp      = (const float*)d_in[4];
    const float* q_scale = (const float*)d_in[5];
    const float* q_bias  = (const float*)d_in[6];
    const float* k_scale = (const float*)d_in[7];
    const float* k_bias  = (const float*)d_in[8];
    const float* v_scale = (const float*)d_in[9];
    const float* v_bias  = (const float*)d_in[10];
    const float* p_scale = (const float*)d_in[11];
    const float* p_bias  = (const float*)d_in[12];
    float* out = (float*)d_out;

    void* p;
    cudaGetSymbolAddress(&p, g_xs);    __half* xs  = (__half*)p;
    cudaGetSymbolAddress(&p, g_qp);    __half* qp  = (__half*)p;
    cudaGetSymbolAddress(&p, g_kp);    __half* kp  = (__half*)p;
    cudaGetSymbolAddress(&p, g_vp);    __half* vp  = (__half*)p;
    cudaGetSymbolAddress(&p, g_qh);    __half* qh  = (__half*)p;
    cudaGetSymbolAddress(&p, g_kh);    __half* kh  = (__half*)p;
    cudaGetSymbolAddress(&p, g_vh);    __half* vh  = (__half*)p;
    cudaGetSymbolAddress(&p, g_oh);    __half* oh  = (__half*)p;
    cudaGetSymbolAddress(&p, g_wq);    __half* wqp = (__half*)p;
    cudaGetSymbolAddress(&p, g_wk);    __half* wkp = (__half*)p;
    cudaGetSymbolAddress(&p, g_wv);    __half* wvp = (__half*)p;
    cudaGetSymbolAddress(&p, g_wp);    __half* wpp = (__half*)p;
    cudaGetSymbolAddress(&p, g_b2d_q); float*  b2q = (float*)p;
    cudaGetSymbolAddress(&p, g_b2d_k); float*  b2k = (float*)p;
    cudaGetSymbolAddress(&p, g_b2d_v); float*  b2v = (float*)p;
    cudaGetSymbolAddress(&p, g_b2d_p); float*  b2p = (float*)p;

    cudaFuncSetAttribute(conv_wmma1<true>,  cudaFuncAttributeMaxDynamicSharedMemorySize, P_SMEM);
    cudaFuncSetAttribute(conv_wmma1<false>, cudaFuncAttributeMaxDynamicSharedMemorySize, P_SMEM);

    const int perT1 = Bd * Cd  * Nd;   //  4,194,304
    const int perTv = Bd * CVd * Nd;   // 16,777,216

    // 0. weight folding (single fp16 term) + bias broadcast tables
    prep_w1<<<(Cd  * Cd  + 255) / 256, 256>>>(wq, q_scale, wqp, Cd,  Cd);
    prep_w1<<<(Cd  * Cd  + 255) / 256, 256>>>(wk, k_scale, wkp, Cd,  Cd);
    prep_w1<<<(CVd * Cd  + 255) / 256, 256>>>(wv, v_scale, wvp, CVd, Cd);
    prep_w1<<<(Cd  * CVd + 255) / 256, 256>>>(wp, p_scale, wpp, Cd,  CVd);
    prep_b<<<(Cd  * 128 + 255) / 256, 256>>>(q_bias, b2q, Cd);
    prep_b<<<(Cd  * 128 + 255) / 256, 256>>>(k_bias, b2k, Cd);
    prep_b<<<(CVd * 128 + 255) / 256, 256>>>(v_bias, b2v, CVd);
    prep_b<<<(Cd  * 128 + 255) / 256, 256>>>(p_bias, b2p, Cd);

    // 1. head spikes (fp16)
    sfa_f2h4<<<perT1 / 4 / 256, 256>>>((const float4*)x, (uint2*)xs, perT1 / 4);

    // 2. q/k/v conv + BN -> fp16 pre-activations
    conv_wmma1<true><<<dim3(2,  4, TBd), 256, P_SMEM>>>(wqp, xs, b2q, qp, Cd,  Cd);
    conv_wmma1<true><<<dim3(2,  4, TBd), 256, P_SMEM>>>(wkp, xs, b2k, kp, Cd,  Cd);
    conv_wmma1<true><<<dim3(2, 16, TBd), 256, P_SMEM>>>(wvp, xs, b2v, vp, CVd, Cd);

    // 3. spike q/k/v (fp16 -> fp16)
    sfa_h2h4<<<perT1 / 4 / 256, 256>>>((const uint2*)qp, (uint2*)qh, perT1 / 4);
    sfa_h2h4<<<perT1 / 4 / 256, 256>>>((const uint2*)kp, (uint2*)kh, perT1 / 4);
    sfa_h2h4<<<perTv / 4 / 256, 256>>>((const uint2*)vp, (uint2*)vh, perTv / 4);

    // 4. linear attention: kv single fp16, O = 0.25 kv^T Q fused SFA
    kv_wmma<<<Zd, 256>>>();
    av_fused<<<dim3(4, 2, Bd * NHd), 256>>>();

    // 5. projection conv + BN -> fp32 output
    conv_wmma1<false><<<dim3(2, 4, TBd), 256, P_SMEM>>>(wpp, oh, b2p, out, Cd, CVd);
}